// round 11
// baseline (speedup 1.0000x reference)
#include <cuda_runtime.h>
#include <cuda_bf16.h>
#include <cstdint>

#define HDIM 512
#define ROWS 64          // rows per CTA
#define NT   512         // 16 warps
#define HBS  520         // bf16 h row stride (elements)
#define AS   512         // int8 hq row stride (bytes), XOR-swizzled units
#define WKP  48          // W chunk row bytes (32 int8 k + 16 pad) -> conflict-free ldmatrix
#define NCH  16          // chunks per GEMM (K=32 int8 each)
#define CHBYTES (512*WKP)     // 24576 B per W chunk
#define NBUF 3

__device__ float g_sf[2][4][HDIM];
__device__ float g_ws[4][HDIM];                       // per-output-row W scales
__device__ __align__(16) int8_t g_wq[4][NCH*CHBYTES]; // int8 W2/W3 (f1,f2), chunked

// ---------------- helpers ----------------
__device__ __forceinline__ uint32_t smem_u32(const void* p){
    uint32_t a;
    asm("{ .reg .u64 t; cvta.to.shared.u64 t, %1; cvt.u32.u64 %0, t; }" : "=r"(a) : "l"(p));
    return a;
}
__device__ __forceinline__ void mbar_wait(uint32_t mbar, uint32_t parity){
    asm volatile(
        "{\n\t.reg .pred P;\n\t"
        "LAB%=:\n\t"
        "mbarrier.try_wait.parity.acquire.cta.shared::cta.b64 P, [%0], %1, 0x989680;\n\t"
        "@!P bra LAB%=;\n\t}"
        :: "r"(mbar), "r"(parity) : "memory");
}
#define MBAR_INIT(a, c)   asm volatile("mbarrier.init.shared.b64 [%0], %1;" :: "r"(a), "r"((uint32_t)(c)) : "memory")
#define MBAR_INVAL(a)     asm volatile("mbarrier.inval.shared.b64 [%0];" :: "r"(a) : "memory")
#define MBAR_EXPECT(a, b) asm volatile("mbarrier.arrive.expect_tx.shared.b64 _, [%0], %1;" :: "r"(a), "r"((uint32_t)(b)) : "memory")
#define MBAR_ARRIVE(a)    asm volatile("mbarrier.arrive.shared.b64 _, [%0];" :: "r"(a) : "memory")
#define BULK_G2S(dst, src, mbar) \
    asm volatile("cp.async.bulk.shared::cluster.global.mbarrier::complete_tx::bytes [%0], [%1], %2, [%3];" \
        :: "r"(dst), "l"(src), "r"((uint32_t)CHBYTES), "r"(mbar) : "memory")
#define LDMX4(r, addr) \
    asm volatile("ldmatrix.sync.aligned.m8n8.x4.shared.b16 {%0,%1,%2,%3}, [%4];" \
        : "=r"((r)[0]), "=r"((r)[1]), "=r"((r)[2]), "=r"((r)[3]) : "r"(addr))
#define MMA_S8(d, a, b0, b1) \
    asm volatile("mma.sync.aligned.m16n8k32.row.col.s32.s8.s8.s32 " \
        "{%0,%1,%2,%3}, {%4,%5,%6,%7}, {%8,%9}, {%0,%1,%2,%3};" \
        : "+r"((d)[0]), "+r"((d)[1]), "+r"((d)[2]), "+r"((d)[3]) \
        : "r"((a)[0]), "r"((a)[1]), "r"((a)[2]), "r"((a)[3]), "r"(b0), "r"(b1))

// ---------------- prep: per-row int8 quantized W2/W3 chunks ----------------
__global__ void prep_w(const float* __restrict__ W2a, const float* __restrict__ W3a,
                       const float* __restrict__ W2b, const float* __restrict__ W3b){
    int mat = blockIdx.y;
    const float* W = mat==0 ? W2a : mat==1 ? W3a : mat==2 ? W2b : W3b;
    int n = blockIdx.x*16 + (threadIdx.x >> 5);
    int lane = threadIdx.x & 31;
    const float4* row = reinterpret_cast<const float4*>(W + n*HDIM);
    float4 v[4]; float am = 0.f;
    #pragma unroll
    for (int i = 0; i < 4; ++i){
        v[i] = row[lane*4 + i];
        am = fmaxf(am, fmaxf(fmaxf(fabsf(v[i].x), fabsf(v[i].y)), fmaxf(fabsf(v[i].z), fabsf(v[i].w))));
    }
    #pragma unroll
    for (int off = 16; off > 0; off >>= 1) am = fmaxf(am, __shfl_xor_sync(0xffffffffu, am, off));
    float qv = am > 0.f ? 127.f/am : 0.f;
    if (lane == 0) g_ws[mat][n] = am * (1.f/127.f);
    #pragma unroll
    for (int i = 0; i < 4; ++i){
        int k = lane*16 + i*4;
        char4 q;
        q.x = (char)__float2int_rn(v[i].x * qv);
        q.y = (char)__float2int_rn(v[i].y * qv);
        q.z = (char)__float2int_rn(v[i].z * qv);
        q.w = (char)__float2int_rn(v[i].w * qv);
        *reinterpret_cast<char4*>(&g_wq[mat][((k>>5)*512 + n)*WKP + (k & 31)]) = q;
    }
    if (lane < 16)
        *reinterpret_cast<int4*>(&g_wq[mat][((size_t)lane*512 + n)*WKP + 32]) = make_int4(0,0,0,0);
}

// sf[f][b][:] = tanh(code[b] @ cond_w^T + cond_b)
__global__ void sf_kernel(const float* __restrict__ code,
                          const float* __restrict__ cw1, const float* __restrict__ cb1,
                          const float* __restrict__ cw2, const float* __restrict__ cb2){
    int b = blockIdx.x, f = blockIdx.y, t = threadIdx.x;
    const float* cw = f ? cw2 : cw1;
    const float* cb = f ? cb2 : cb1;
    const float4* c4 = reinterpret_cast<const float4*>(code + b*HDIM);
    const float4* w4 = reinterpret_cast<const float4*>(cw + t*HDIM);
    float s = 0.f;
    #pragma unroll 4
    for (int i = 0; i < HDIM/4; i++){
        float4 a = c4[i], w = w4[i];
        s = fmaf(a.x, w.x, fmaf(a.y, w.y, fmaf(a.z, w.z, fmaf(a.w, w.w, s))));
    }
    g_sf[f][b][t] = tanhf(s + cb[t]);
}

__global__ __launch_bounds__(NT, 1)
void deform_kernel(const float* __restrict__ x_in, float* __restrict__ x_out,
    const float* __restrict__ W1a, const float* __restrict__ b1a,
    const float* __restrict__ b2a, const float* __restrict__ b3a,
    const float* __restrict__ W4a, const float* __restrict__ b4a,
    const float* __restrict__ W1b, const float* __restrict__ b1b,
    const float* __restrict__ b2b, const float* __restrict__ b3b,
    const float* __restrict__ W4b, const float* __restrict__ b4b)
{
    extern __shared__ char dsm[];
    uintptr_t pa = (reinterpret_cast<uintptr_t>(dsm) + 1023) & ~(uintptr_t)1023;
    char* hq  = reinterpret_cast<char*>(pa);            // 64 x 512 int8, swizzled 16B units
    char* hb  = hq + ROWS*AS;                           // 64 x 520 bf16 = 66560 B
    char* wc  = hb + ROWS*HBS*2;                        // 3 x 24576 B
    float* msc = reinterpret_cast<float*>(wc + NBUF*CHBYTES);
    float* sfs  = msc;
    float* b1s  = msc + 512;
    float* b2s  = msc + 1024;
    float* b3s  = msc + 1536;
    float* w1xs = msc + 2048;
    float* w1ys = msc + 2560;
    float* w1zs = msc + 3072;
    float* w4s  = msc + 3584;   // 3*512
    float* ws2  = msc + 5120;
    float* ws3  = msc + 5632;   // total 6144 floats

    uint32_t* hb2 = reinterpret_cast<uint32_t*>(hb);    // bf16-pair view, stride HBS/2

    __shared__ __align__(8) unsigned long long mbarF_s[NBUF], mbarE_s[NBUF];
    __shared__ float p0[ROWS][3], pe[ROWS][3], ksum[ROWS][3], kcur[ROWS][3];
    __shared__ float ds[ROWS], qm[ROWS];
    __shared__ float pmax[ROWS][8];

    const int tid = threadIdx.x;
    const int wid = tid >> 5, lane = tid & 31;
    const int g = lane >> 2, tig = lane & 3;
    const int cw = wid >> 1;
    const int rbase = (wid & 1) * 32;
    const int colbase = (wid >> 1) * 64;
    const int base = blockIdx.x * ROWS;
    const int b = base >> 12;

    const uint32_t hq_u32 = smem_u32(hq);
    const uint32_t wc_u32 = smem_u32(wc);
    const uint32_t mbarF = smem_u32(&mbarF_s[0]);
    const uint32_t mbarE = smem_u32(&mbarE_s[0]);

    const uint32_t a_lrow = (uint32_t)(lane & 15);
    const uint32_t a_ku   = (uint32_t)((lane >> 4) & 1);       // extra 16B unit in k
    const uint32_t b_lrow = (uint32_t)((lane & 7) + ((lane & 16) ? 8 : 0));
    const uint32_t b_k16  = (lane & 8) ? 16u : 0u;             // byte offset

    if (tid == 0){
        #pragma unroll
        for (int j = 0; j < NBUF; ++j){
            MBAR_INIT(mbarF + j*8, 1);
            MBAR_INIT(mbarE + j*8, 16);
        }
    }
    if (tid < ROWS*3){
        int r = tid/3, j = tid - r*3;
        float v = x_in[(base + r)*3 + j];
        p0[r][j] = v; pe[r][j] = v;
    }
    __syncthreads();

    uint32_t gb = 0;
    uint32_t cful = 0;
    uint32_t pemp = 0x7;

    const float dt = 0.05f;

    for (int f = 0; f < 2; ++f){
        const float* W1 = f ? W1b : W1a;
        const float* B1 = f ? b1b : b1a;
        const float* B2 = f ? b2b : b2a;
        const float* B3 = f ? b3b : b3a;
        const float* W4 = f ? W4b : W4a;
        const float* B4 = f ? b4b : b4a;
        const int8_t* Wq2 = g_wq[f*2 + 0];
        const int8_t* Wq3 = g_wq[f*2 + 1];

        __syncthreads();
        {
            int c = tid;
            sfs[c]  = g_sf[f][b][c];
            b1s[c]  = B1[c]; b2s[c] = B2[c]; b3s[c] = B3[c];
            w1xs[c] = W1[c*3+0]; w1ys[c] = W1[c*3+1]; w1zs[c] = W1[c*3+2];
            w4s[c]        = W4[c];
            w4s[512 + c]  = W4[512 + c];
            w4s[1024 + c] = W4[1024 + c];
            ws2[c] = g_ws[f*2 + 0][c];
            ws3[c] = g_ws[f*2 + 1][c];
        }
        __syncthreads();

        auto issue = [&](int t){
            uint32_t j = (gb + (uint32_t)t) % NBUF;
            mbar_wait(mbarE + j*8, (pemp >> j) & 1u);
            pemp ^= (1u << j);
            MBAR_EXPECT(mbarF + j*8, CHBYTES);
            const int8_t* src = (t < NCH) ? (Wq2 + (size_t)t*CHBYTES)
                                          : (Wq3 + (size_t)(t - NCH)*CHBYTES);
            BULK_G2S(wc_u32 + j*CHBYTES, src, mbarF + j*8);
        };

        for (int step = 0; step < 4; ++step){
            for (int s = 0; s < 4; ++s){
                if (tid == 0){ issue(0); issue(1); }

                // ---- stage 1: h = relu(pe @ W1^T + b1) * sf; bf16 + int8-quant per row
                #pragma unroll
                for (int rr = 0; rr < 4; ++rr){
                    int r = wid*4 + rr;
                    float px = pe[r][0], py = pe[r][1], pz = pe[r][2];
                    float vals[16]; float am = 0.f;
                    #pragma unroll
                    for (int cc = 0; cc < 4; ++cc){
                        int c4 = cc*128 + lane*4;
                        float4 wx = *reinterpret_cast<const float4*>(&w1xs[c4]);
                        float4 wy = *reinterpret_cast<const float4*>(&w1ys[c4]);
                        float4 wz = *reinterpret_cast<const float4*>(&w1zs[c4]);
                        float4 bb = *reinterpret_cast<const float4*>(&b1s[c4]);
                        float4 sf4 = *reinterpret_cast<const float4*>(&sfs[c4]);
                        float o0 = fmaxf(fmaf(px, wx.x, fmaf(py, wy.x, fmaf(pz, wz.x, bb.x))), 0.f) * sf4.x;
                        float o1 = fmaxf(fmaf(px, wx.y, fmaf(py, wy.y, fmaf(pz, wz.y, bb.y))), 0.f) * sf4.y;
                        float o2 = fmaxf(fmaf(px, wx.z, fmaf(py, wy.z, fmaf(pz, wz.z, bb.z))), 0.f) * sf4.z;
                        float o3 = fmaxf(fmaf(px, wx.w, fmaf(py, wy.w, fmaf(pz, wz.w, bb.w))), 0.f) * sf4.w;
                        vals[cc*4+0]=o0; vals[cc*4+1]=o1; vals[cc*4+2]=o2; vals[cc*4+3]=o3;
                        am = fmaxf(am, fmaxf(fmaxf(fabsf(o0), fabsf(o1)), fmaxf(fabsf(o2), fabsf(o3))));
                        __nv_bfloat162 pA = __floats2bfloat162_rn(o0, o1);
                        __nv_bfloat162 pB = __floats2bfloat162_rn(o2, o3);
                        uint2 pk = make_uint2(*reinterpret_cast<uint32_t*>(&pA),
                                              *reinterpret_cast<uint32_t*>(&pB));
                        *reinterpret_cast<uint2*>(&hb2[r*(HBS/2) + (c4 >> 1)]) = pk;
                    }
                    #pragma unroll
                    for (int off = 16; off > 0; off >>= 1) am = fmaxf(am, __shfl_xor_sync(0xffffffffu, am, off));
                    float qv = am > 0.f ? 127.f/am : 0.f;
                    if (lane == 0){ ds[r] = am * (1.f/127.f); }
                    #pragma unroll
                    for (int cc = 0; cc < 4; ++cc){
                        int c4 = cc*128 + lane*4;
                        char4 q;
                        q.x = (char)__float2int_rn(vals[cc*4+0] * qv);
                        q.y = (char)__float2int_rn(vals[cc*4+1] * qv);
                        q.z = (char)__float2int_rn(vals[cc*4+2] * qv);
                        q.w = (char)__float2int_rn(vals[cc*4+3] * qv);
                        int unit = (c4 >> 4) ^ (r & 7);
                        *reinterpret_cast<char4*>(hq + r*AS + (unit << 4) + (c4 & 15)) = q;
                    }
                }
                __syncthreads();   // hq/hb/ds published

                // ---- two residual GEMMs via int8 IMMA
                #pragma unroll 1
                for (int gg = 0; gg < 2; ++gg){
                    const float* bias_s = gg ? b3s : b2s;
                    const float* ws_s   = gg ? ws3 : ws2;

                    int acc[2][8][4];
                    #pragma unroll
                    for (int m = 0; m < 2; ++m)
                        #pragma unroll
                        for (int j = 0; j < 8; ++j)
                            #pragma unroll
                            for (int q = 0; q < 4; ++q) acc[m][j][q] = 0;

                    #pragma unroll 1
                    for (int c = 0; c < NCH; ++c){
                        const int t = gg*NCH + c;
                        if (tid == 0 && t + 2 < 2*NCH) issue(t + 2);

                        uint32_t j = (gb + (uint32_t)t) % NBUF;
                        mbar_wait(mbarF + j*8, (cful >> j) & 1u);
                        cful ^= (1u << j);
                        const uint32_t wcu = wc_u32 + j*CHBYTES;

                        uint32_t Afr[2][4];
                        #pragma unroll
                        for (int m = 0; m < 2; ++m){
                            uint32_t row = (uint32_t)(rbase + 16*m) + a_lrow;
                            uint32_t unit = (uint32_t)((c*2 + (int)a_ku) ^ (int)(row & 7));
                            LDMX4(Afr[m], hq_u32 + (row << 9) + (unit << 4));
                        }
                        #pragma unroll
                        for (int jj = 0; jj < 4; ++jj){
                            uint32_t Bf[4];
                            uint32_t addr = wcu + ((uint32_t)(colbase + 16*jj) + b_lrow)*WKP + b_k16;
                            LDMX4(Bf, addr);
                            MMA_S8(acc[0][2*jj],   Afr[0], Bf[0], Bf[1]);
                            MMA_S8(acc[0][2*jj+1], Afr[0], Bf[2], Bf[3]);
                            MMA_S8(acc[1][2*jj],   Afr[1], Bf[0], Bf[1]);
                            MMA_S8(acc[1][2*jj+1], Afr[1], Bf[2], Bf[3]);
                        }
                        if (lane == 0) MBAR_ARRIVE(mbarE + j*8);
                    }
                    __syncthreads();

                    // ---- epilogue phase 1: dequant + relu + bias + residual; bf16 store
                    float ds4[2][2], pm[2][2];
                    #pragma unroll
                    for (int m = 0; m < 2; ++m)
                        #pragma unroll
                        for (int hh = 0; hh < 2; ++hh){
                            ds4[m][hh] = ds[rbase + 16*m + g + 8*hh];
                            pm[m][hh] = 0.f;
                        }
                    #pragma unroll
                    for (int m = 0; m < 2; ++m){
                        #pragma unroll
                        for (int j = 0; j < 8; ++j){
                            int cc = colbase + 8*j + 2*tig;
                            float w0 = ws_s[cc], w1 = ws_s[cc+1];
                            float bi0 = bias_s[cc], bi1 = bias_s[cc+1];
                            #pragma unroll
                            for (int hh = 0; hh < 2; ++hh){
                                int row = rbase + 16*m + g + 8*hh;
                                float sc = ds4[m][hh];
                                uint32_t* hp = &hb2[row*(HBS/2) + (cc >> 1)];
                                __nv_bfloat162 old = *reinterpret_cast<__nv_bfloat162*>(hp);
                                float nx = fmaxf((float)acc[m][j][2*hh]   * sc * w0 + bi0, 0.f) + __bfloat162float(old.x);
                                float ny = fmaxf((float)acc[m][j][2*hh+1] * sc * w1 + bi1, 0.f) + __bfloat162float(old.y);
                                __nv_bfloat162 nv = __floats2bfloat162_rn(nx, ny);
                                *hp = *reinterpret_cast<uint32_t*>(&nv);
                                acc[m][j][2*hh]   = __float_as_int(nx);
                                acc[m][j][2*hh+1] = __float_as_int(ny);
                                pm[m][hh] = fmaxf(pm[m][hh], fmaxf(fabsf(nx), fabsf(ny)));
                            }
                        }
                    }
                    if (gg == 0){
                        // row-max reduction across tig, then col-warps
                        #pragma unroll
                        for (int m = 0; m < 2; ++m)
                            #pragma unroll
                            for (int hh = 0; hh < 2; ++hh){
                                float v = pm[m][hh];
                                v = fmaxf(v, __shfl_xor_sync(0xffffffffu, v, 1));
                                v = fmaxf(v, __shfl_xor_sync(0xffffffffu, v, 2));
                                if (tig == 0) pmax[rbase + 16*m + g + 8*hh][cw] = v;
                            }
                        __syncthreads();
                        if (tid < ROWS){
                            float mx = pmax[tid][0];
                            #pragma unroll
                            for (int i = 1; i < 8; ++i) mx = fmaxf(mx, pmax[tid][i]);
                            ds[tid] = mx * (1.f/127.f);
                            qm[tid] = mx > 0.f ? 127.f/mx : 0.f;
                        }
                        __syncthreads();
                        // quantize into hq
                        #pragma unroll
                        for (int m = 0; m < 2; ++m){
                            #pragma unroll
                            for (int j = 0; j < 8; ++j){
                                int cc = colbase + 8*j + 2*tig;
                                #pragma unroll
                                for (int hh = 0; hh < 2; ++hh){
                                    int row = rbase + 16*m + g + 8*hh;
                                    float qv = qm[row];
                                    int q0 = __float2int_rn(__int_as_float(acc[m][j][2*hh])   * qv);
                                    int q1 = __float2int_rn(__int_as_float(acc[m][j][2*hh+1]) * qv);
                                    uint16_t pk = (uint16_t)((q0 & 0xff) | ((q1 & 0xff) << 8));
                                    int unit = (cc >> 4) ^ (row & 7);
                                    *reinterpret_cast<uint16_t*>(hq + row*AS + (unit << 4) + (cc & 15)) = pk;
                                }
                            }
                        }
                        __syncthreads();
                    } else {
                        __syncthreads();
                    }
                }
                gb += 2*NCH;

                // ---- stage 4: kcur = tanh(h @ W4^T + b4); warp w -> rows 4w..4w+3
                {
                    float a[4][3];
                    #pragma unroll
                    for (int rr = 0; rr < 4; ++rr){ a[rr][0]=0.f; a[rr][1]=0.f; a[rr][2]=0.f; }
                    #pragma unroll 2
                    for (int i = 0; i < 8; ++i){
                        int idx = lane + i*32;
                        float w00 = w4s[2*idx],        w01 = w4s[2*idx+1];
                        float w10 = w4s[512 + 2*idx],  w11 = w4s[512 + 2*idx+1];
                        float w20 = w4s[1024 + 2*idx], w21 = w4s[1024 + 2*idx+1];
                        #pragma unroll
                        for (int rr = 0; rr < 4; ++rr){
                            uint32_t pv = hb2[(wid*4 + rr)*(HBS/2) + idx];
                            __nv_bfloat162 hv = *reinterpret_cast<__nv_bfloat162*>(&pv);
                            float hx = __bfloat162float(hv.x), hy = __bfloat162float(hv.y);
                            a[rr][0] = fmaf(hx, w00, fmaf(hy, w01, a[rr][0]));
                            a[rr][1] = fmaf(hx, w10, fmaf(hy, w11, a[rr][1]));
                            a[rr][2] = fmaf(hx, w20, fmaf(hy, w21, a[rr][2]));
                        }
                    }
                    #pragma unroll
                    for (int rr = 0; rr < 4; ++rr){
                        #pragma unroll
                        for (int j = 0; j < 3; ++j){
                            float v = a[rr][j];
                            #pragma unroll
                            for (int off = 16; off > 0; off >>= 1)
                                v += __shfl_xor_sync(0xffffffffu, v, off);
                            if (lane == 0) kcur[wid*4 + rr][j] = tanhf(v + B4[j]);
                        }
                    }
                }
                __syncthreads();

                // ---- RK4 state update
                if (tid < ROWS*3){
                    int r = tid/3, j = tid - r*3;
                    float k = kcur[r][j];
                    if (s == 0){ ksum[r][j] = k;            pe[r][j] = fmaf(0.5f*dt, k, p0[r][j]); }
                    else if (s == 1){ ksum[r][j] += 2.f*k;  pe[r][j] = fmaf(0.5f*dt, k, p0[r][j]); }
                    else if (s == 2){ ksum[r][j] += 2.f*k;  pe[r][j] = fmaf(dt, k, p0[r][j]); }
                    else { float p = fmaf(dt/6.f, ksum[r][j] + k, p0[r][j]); p0[r][j] = p; pe[r][j] = p; }
                }
                __syncthreads();
            }
        }
    }

    if (tid < ROWS*3){
        int r = tid/3, j = tid - r*3;
        x_out[(base + r)*3 + j] = p0[r][j];
    }
    __syncthreads();
    if (tid == 0){
        #pragma unroll
        for (int j = 0; j < NBUF; ++j){ MBAR_INVAL(mbarF + j*8); MBAR_INVAL(mbarE + j*8); }
    }
}

extern "C" void kernel_launch(void* const* d_in, const int* in_sizes, int n_in,
                              void* d_out, int out_size)
{
    const float* code   = (const float*)d_in[0];
    const float* x      = (const float*)d_in[1];
    const float* f1_l1w = (const float*)d_in[2];
    const float* f1_l1b = (const float*)d_in[3];
    const float* f1_l2w = (const float*)d_in[4];
    const float* f1_l2b = (const float*)d_in[5];
    const float* f1_l3w = (const float*)d_in[6];
    const float* f1_l3b = (const float*)d_in[7];
    const float* f1_l4w = (const float*)d_in[8];
    const float* f1_l4b = (const float*)d_in[9];
    const float* f1_cw  = (const float*)d_in[10];
    const float* f1_cb  = (const float*)d_in[11];
    const float* f2_l1w = (const float*)d_in[12];
    const float* f2_l1b = (const float*)d_in[13];
    const float* f2_l2w = (const float*)d_in[14];
    const float* f2_l2b = (const float*)d_in[15];
    const float* f2_l3w = (const float*)d_in[16];
    const float* f2_l3b = (const float*)d_in[17];
    const float* f2_l4w = (const float*)d_in[18];
    const float* f2_l4b = (const float*)d_in[19];
    const float* f2_cw  = (const float*)d_in[20];
    const float* f2_cb  = (const float*)d_in[21];
    float* out = (float*)d_out;

    const int smem_bytes = 1024 + ROWS*AS + ROWS*HBS*2 + NBUF*CHBYTES + 6144*4;  // ~198 KB
    cudaFuncSetAttribute(deform_kernel, cudaFuncAttributeMaxDynamicSharedMemorySize, smem_bytes);

    prep_w<<<dim3(32, 4), NT>>>(f1_l2w, f1_l3w, f2_l2w, f2_l3w);
    sf_kernel<<<dim3(4, 2), HDIM>>>(code, f1_cw, f1_cb, f2_cw, f2_cb);

    const int n_blocks = (4 * 4096) / ROWS;  // 256
    deform_kernel<<<n_blocks, NT, smem_bytes>>>(
        x, out,
        f1_l1w, f1_l1b, f1_l2b, f1_l3b, f1_l4w, f1_l4b,
        f2_l1w, f2_l1b, f2_l2b, f2_l3b, f2_l4w, f2_l4b);
}